// round 12
// baseline (speedup 1.0000x reference)
#include <cuda_runtime.h>
#include <cuda_fp16.h>
#include <cstdint>

// ---------------------------------------------------------------------------
// BasisConvLayer (mode='conv', linear hat basis 4x4, F_in=F_out=16)
//
// FP16 table  T[node][u:4][v:4][fout:16]  (512 B/node, 51 MB).
//   Kernel 1 (build): warp per 8-node batch; lane <-> (cell k, fout-half h);
//     W column in f32x2 regs; x staged once per batch as duplicated f32x2
//     pairs in smem; per node: 8 LDS.128 + 64 FFMA2 + 1 STG.128 (512B/warp).
//   Kernel 2 (edge): R6-proven config: 4 lanes/edge x 2 edges/thread;
//     table loads with createpolicy L2::evict_last cache hint;
//     split shfl_xor(2) combine; red.global.add.v4.
// ---------------------------------------------------------------------------

#define MAX_NODES 100000
#define F 16
#define NB 4
#define TROWH 256                 // halves per node

__device__ __align__(512) __half g_table[(size_t)MAX_NODES * TROWH];

#define PACK_F32X2(out, lo, hi) \
    asm("mov.b64 %0, {%1, %2};" : "=l"(out) : "f"(lo), "f"(hi))
#define UNPACK_F32X2(lo, hi, in) \
    asm("mov.b64 {%0, %1}, %2;" : "=f"(lo), "=f"(hi) : "l"(in))
#define FMA_F32X2(d, a, b, c) \
    asm("fma.rn.f32x2 %0, %1, %2, %3;" : "=l"(d) : "l"(a), "l"(b), "l"(c))
// memory halves order [lo, hi]
#define CVT_F16X2(u, lo, hi) \
    asm("cvt.rn.f16x2.f32 %0, %1, %2;" : "=r"(u) : "f"(hi), "f"(lo))

#define XPS 18                    // u64 stride per node (even -> 16B align)

// ---------------------------------------------------------------------------
// Kernel 1: build.
// ---------------------------------------------------------------------------
__global__ void build_table_kernel(
    const float* __restrict__ x,
    const float* __restrict__ w,
    int n_nodes)
{
    __shared__ __align__(16) unsigned long long xp[4][8 * XPS];

    int lane  = threadIdx.x & 31;
    int warpL = threadIdx.x >> 5;
    int warpG = blockIdx.x * 4 + warpL;
    int k     = lane >> 1;             // cell 0..15
    int h     = lane & 1;              // fout half (8 fouts)

    // W pairs: wp[fin][j] covers fouts h*8 + 2j, 2j+1
    const float4* wf4 = reinterpret_cast<const float4*>(w);
    unsigned long long wp[F][4];
#pragma unroll
    for (int fin = 0; fin < F; fin++) {
        float4 wA = wf4[k * 64 + fin * 4 + h * 2];
        float4 wB = wf4[k * 64 + fin * 4 + h * 2 + 1];
        PACK_F32X2(wp[fin][0], wA.x, wA.y);
        PACK_F32X2(wp[fin][1], wA.z, wA.w);
        PACK_F32X2(wp[fin][2], wB.x, wB.y);
        PACK_F32X2(wp[fin][3], wB.z, wB.w);
    }

    const float4* xf4 = reinterpret_cast<const float4*>(x);
    uint4* tb4 = reinterpret_cast<uint4*>(g_table);

    int n_warps  = gridDim.x * 4;
    int n_groups = (n_nodes + 7) >> 3;

    int my_node_off = lane >> 2;     // 0..7 node within batch
    int my_part     = lane & 3;      // float4 within node

    float4 xb_next = make_float4(0.f, 0.f, 0.f, 0.f);
    {
        int n = warpG * 8 + my_node_off;
        if (warpG < n_groups && n < n_nodes)
            xb_next = xf4[(size_t)n * 4 + my_part];
    }

    for (int grp = warpG; grp < n_groups; grp += n_warps) {
        float4 xb = xb_next;
        {
            int ng = grp + n_warps;
            int n  = ng * 8 + my_node_off;
            if (ng < n_groups && n < n_nodes)
                xb_next = xf4[(size_t)n * 4 + my_part];
        }

        // stage duplicated pairs: xp[warp][node*XPS + fin] = (v, v)
        {
            unsigned long long p0, p1, p2, p3;
            PACK_F32X2(p0, xb.x, xb.x);
            PACK_F32X2(p1, xb.y, xb.y);
            PACK_F32X2(p2, xb.z, xb.z);
            PACK_F32X2(p3, xb.w, xb.w);
            int base = my_node_off * XPS + my_part * 4;
            xp[warpL][base + 0] = p0;
            xp[warpL][base + 1] = p1;
            xp[warpL][base + 2] = p2;
            xp[warpL][base + 3] = p3;
        }
        __syncwarp();

#pragma unroll
        for (int nl = 0; nl < 8; nl++) {
            int node = grp * 8 + nl;
            const ulonglong2* xrow = reinterpret_cast<const ulonglong2*>(
                &xp[warpL][nl * XPS]);
            unsigned long long a0 = 0, a1 = 0, a2 = 0, a3 = 0;
#pragma unroll
            for (int f2 = 0; f2 < 8; f2++) {
                ulonglong2 xx = xrow[f2];            // LDS.128 broadcast
                FMA_F32X2(a0, xx.x, wp[2 * f2][0], a0);
                FMA_F32X2(a1, xx.x, wp[2 * f2][1], a1);
                FMA_F32X2(a2, xx.x, wp[2 * f2][2], a2);
                FMA_F32X2(a3, xx.x, wp[2 * f2][3], a3);
                FMA_F32X2(a0, xx.y, wp[2 * f2 + 1][0], a0);
                FMA_F32X2(a1, xx.y, wp[2 * f2 + 1][1], a1);
                FMA_F32X2(a2, xx.y, wp[2 * f2 + 1][2], a2);
                FMA_F32X2(a3, xx.y, wp[2 * f2 + 1][3], a3);
            }
            if (node < n_nodes) {
                float f0, f1, f2, f3;
                uint4 val;
                UNPACK_F32X2(f0, f1, a0);
                UNPACK_F32X2(f2, f3, a1);
                CVT_F16X2(val.x, f0, f1);
                CVT_F16X2(val.y, f2, f3);
                UNPACK_F32X2(f0, f1, a2);
                UNPACK_F32X2(f2, f3, a3);
                CVT_F16X2(val.z, f0, f1);
                CVT_F16X2(val.w, f2, f3);
                // uint4 index: node*32 + k*2 + h -> warp covers 512B run
                tb4[(size_t)node * 32 + k * 2 + h] = val;
            }
        }
        __syncwarp();
    }
}

// ---------------------------------------------------------------------------
// Kernel 2: edge (R6-proven) + evict_last cache-hint table loads.
// ---------------------------------------------------------------------------
#define EPB 128
__global__ __launch_bounds__(256) void edge_kernel(
    const int* __restrict__ ei,
    const float* __restrict__ attr,
    float* __restrict__ out,
    int n_edges)
{
    int tid = threadIdx.x;
    int sl  = tid & 3;
    int g   = tid >> 2;

    unsigned long long pol;
    asm("createpolicy.fractional.L2::evict_last.b64 %0, 1.0;" : "=l"(pol));

    const uint4* tb = reinterpret_cast<const uint4*>(g_table);

    int  e[2];
    e[0] = (int)(blockIdx.x * EPB) + g;
    e[1] = e[0] + 64;
    bool val[2];
    int  row[2];
    uint4 u0[2], u1[2];
    float wa[2], wb[2];

#pragma unroll
    for (int i = 0; i < 2; i++) {
        val[i] = (e[i] < n_edges);
        int ec = val[i] ? e[i] : (n_edges - 1);

        row[i]   = ei[ec];
        int col  = ei[n_edges + ec];
        float2 a = reinterpret_cast<const float2*>(attr)[ec];

        float sx = fmaf(a.x, 1.5f, 1.5f);
        float sy = fmaf(a.y, 1.5f, 1.5f);
        float ixf = fminf(fmaxf(floorf(sx), 0.f), 2.f);
        float iyf = fminf(fmaxf(floorf(sy), 0.f), 2.f);
        float fx = sx - ixf;
        float fy = sy - iyf;
        int iu = (int)ixf;
        int iv = (int)iyf;

        float w11 = fx * fy;
        float w10 = fx - w11;
        float w01 = fy - w11;
        float w00 = 1.f - fx - fy + w11;

        wa[i] = (sl < 2) ? w00 : w01;   // u = iu
        wb[i] = (sl < 2) ? w10 : w11;   // u = iu+1

        const uint4* p0 = tb + ((size_t)col * 32 + (iu * 4 + iv) * 2 + sl);
        asm volatile(
            "ld.global.nc.L2::cache_hint.v4.u32 {%0,%1,%2,%3}, [%4], %5;"
            : "=r"(u0[i].x), "=r"(u0[i].y), "=r"(u0[i].z), "=r"(u0[i].w)
            : "l"(p0), "l"(pol));
        asm volatile(
            "ld.global.nc.L2::cache_hint.v4.u32 {%0,%1,%2,%3}, [%4], %5;"
            : "=r"(u1[i].x), "=r"(u1[i].y), "=r"(u1[i].z), "=r"(u1[i].w)
            : "l"(p0 + 8), "l"(pol));
    }

#pragma unroll
    for (int i = 0; i < 2; i++) {
        const __half2* h0 = reinterpret_cast<const __half2*>(&u0[i]);
        const __half2* h1 = reinterpret_cast<const __half2*>(&u1[i]);
        float p[8];
#pragma unroll
        for (int j = 0; j < 4; j++) {
            float2 f0 = __half22float2(h0[j]);
            float2 f1 = __half22float2(h1[j]);
            p[2 * j]     = fmaf(wa[i], f0.x, wb[i] * f1.x);
            p[2 * j + 1] = fmaf(wa[i], f0.y, wb[i] * f1.y);
        }
        bool hi = (sl & 2);
        float fin0, fin1, fin2, fin3;
        {
            float s0 = hi ? p[0] : p[4];
            float s1 = hi ? p[1] : p[5];
            float s2 = hi ? p[2] : p[6];
            float s3 = hi ? p[3] : p[7];
            float r0 = __shfl_xor_sync(0xffffffffu, s0, 2);
            float r1 = __shfl_xor_sync(0xffffffffu, s1, 2);
            float r2 = __shfl_xor_sync(0xffffffffu, s2, 2);
            float r3 = __shfl_xor_sync(0xffffffffu, s3, 2);
            fin0 = (hi ? p[4] : p[0]) + r0;
            fin1 = (hi ? p[5] : p[1]) + r1;
            fin2 = (hi ? p[6] : p[2]) + r2;
            fin3 = (hi ? p[7] : p[3]) + r3;
        }
        if (val[i]) {
            int quad = (sl & 1) * 2 + (sl >> 1);
            float* op = out + (size_t)row[i] * F + quad * 4;
            asm volatile("red.global.add.v4.f32 [%0], {%1, %2, %3, %4};"
                         :: "l"(op), "f"(fin0), "f"(fin1), "f"(fin2), "f"(fin3)
                         : "memory");
        }
    }
}

// ---------------------------------------------------------------------------
extern "C" void kernel_launch(void* const* d_in, const int* in_sizes, int n_in,
                              void* d_out, int out_size)
{
    const float* x    = (const float*)d_in[0];
    const int*   ei   = (const int*)d_in[1];
    const float* attr = (const float*)d_in[2];
    const float* w    = (const float*)d_in[3];
    float*       out  = (float*)d_out;

    int n_nodes = in_sizes[0] / F;       // 100000
    int n_edges = in_sizes[1] / 2;       // 1600000

    cudaMemsetAsync(d_out, 0, (size_t)out_size * sizeof(float));

    build_table_kernel<<<1184, 128>>>(x, w, n_nodes);

    int ek_blocks = (n_edges + EPB - 1) / EPB;
    edge_kernel<<<ek_blocks, 256>>>(ei, attr, out, n_edges);
}

// round 13
// speedup vs baseline: 1.1034x; 1.1034x over previous
#include <cuda_runtime.h>
#include <cuda_fp16.h>
#include <cstdint>

// ---------------------------------------------------------------------------
// BasisConvLayer (mode='conv', linear hat basis 4x4, F_in=F_out=16)
//
// FP16 table  T[node][u:4][v:4][fout:16]  (512 B/node, 51 MB).
//   Kernel 1 (build) = GEMM X[100K,16] @ W'[16,256] on tensor cores:
//     mma.sync.m16n8k16 (fp16 in, fp32 acc). Per block-iter: 4 M-tiles of 16
//     nodes; warp-pair per tile (n-halves of 128). A via ldmatrix.x4 from
//     smem; W fragments in regs (built once); D -> fp16 -> padded smem
//     (528B rows, bank-conflict-free) -> coalesced uint4 stores.
//   Kernel 2 (edge): R6/R12-proven: 4 lanes/edge x 2 edges/thread;
//     2 LDG.128/lane; split shfl_xor(2) combine; red.global.add.v4.
// ---------------------------------------------------------------------------

#define MAX_NODES 100000
#define F 16
#define TROWH 256                 // halves per node

__device__ __align__(512) __half g_table[(size_t)MAX_NODES * TROWH];

// memory halves order [lo, hi]
#define CVT_F16X2(u, lo, hi) \
    asm("cvt.rn.f16x2.f32 %0, %1, %2;" : "=r"(u) : "f"(hi), "f"(lo))

// ---------------------------------------------------------------------------
// Kernel 1: tensor-core build.
//   A tile (16 nodes x 16 fin) fp16 in smem, 32B rows.
//   B frag (fin16 x n8), n = cell*16 + fout in [0,256): lane l covers
//     n = 8t + (l>>2); k rows (l&3)*2(+1) and +8.
//   D (16 x n8): lane l rows l>>2, l>>2+8; cols (l&3)*2, +1.
// ---------------------------------------------------------------------------
#define OROW 528                    // padded smem row bytes (16 nodes/tile)
#define OTILE (16 * OROW)           // 8448 B per M-tile

__global__ __launch_bounds__(256) void build_table_kernel(
    const float* __restrict__ x,
    const float* __restrict__ w,
    int n_nodes)
{
    __shared__ __align__(16) char smemA[4 * 512];     // 4 tiles x 16x16 fp16
    __shared__ __align__(16) char smemO[4 * OTILE];   // 33792 B

    int tid  = threadIdx.x;
    int lane = tid & 31;
    int wrp  = tid >> 5;
    int m    = wrp >> 1;            // M-tile slot 0..3
    int h    = wrp & 1;             // n-half: cols h*128 .. h*128+127

    // ---- build B fragments once: 16 n8-tiles for this half ----
    unsigned bf0[16], bf1[16];
    {
        int k0 = (lane & 3) * 2;
#pragma unroll
        for (int t = 0; t < 16; t++) {
            int n    = h * 128 + t * 8 + (lane >> 2);
            int cell = n >> 4;
            int fo   = n & 15;
            const float* wc = w + cell * 256 + fo;
            float f0 = wc[k0 * 16];
            float f1 = wc[(k0 + 1) * 16];
            float f2 = wc[(k0 + 8) * 16];
            float f3 = wc[(k0 + 9) * 16];
            CVT_F16X2(bf0[t], f0, f1);
            CVT_F16X2(bf1[t], f2, f3);
        }
    }

    const float4* xf4 = reinterpret_cast<const float4*>(x);
    uint4* tb4 = reinterpret_cast<uint4*>(g_table);

    int n_tiles = (n_nodes + 15) >> 4;

    for (int bt = blockIdx.x * 4; bt < n_tiles; bt += gridDim.x * 4) {
        __syncthreads();   // smem reuse guard vs previous readout

        // ---- stage x tile: 64 nodes, fp32 -> fp16 ----
        {
            int nloc = tid >> 2;
            int part = tid & 3;
            int node = bt * 16 + nloc;
            uint2 v2 = make_uint2(0u, 0u);
            if (node < n_nodes) {
                float4 v = xf4[(size_t)node * 4 + part];
                CVT_F16X2(v2.x, v.x, v.y);
                CVT_F16X2(v2.y, v.z, v.w);
            }
            *reinterpret_cast<uint2*>(
                smemA + (nloc >> 4) * 512 + (nloc & 15) * 32 + part * 8) = v2;
        }
        __syncthreads();

        // ---- A fragments via ldmatrix.x4 ----
        unsigned a0, a1, a2, a3;
        {
            unsigned sa = (unsigned)__cvta_generic_to_shared(
                smemA + m * 512 + (lane & 15) * 32 + (lane >> 4) * 16);
            asm volatile(
                "ldmatrix.sync.aligned.m8n8.x4.shared.b16 {%0,%1,%2,%3}, [%4];"
                : "=r"(a0), "=r"(a1), "=r"(a2), "=r"(a3) : "r"(sa));
        }

        // ---- 16 HMMA in two halves of 8 (regs), pack + STS ----
        char* ob = smemO + m * OTILE;
        int row = lane >> 2;
#pragma unroll
        for (int half = 0; half < 2; half++) {
            float d[8][4];
#pragma unroll
            for (int tt = 0; tt < 8; tt++) {
                int t = half * 8 + tt;
                d[tt][0] = 0.f; d[tt][1] = 0.f; d[tt][2] = 0.f; d[tt][3] = 0.f;
                asm volatile(
                    "mma.sync.aligned.m16n8k16.row.col.f32.f16.f16.f32 "
                    "{%0,%1,%2,%3}, {%4,%5,%6,%7}, {%8,%9}, {%0,%1,%2,%3};"
                    : "+f"(d[tt][0]), "+f"(d[tt][1]),
                      "+f"(d[tt][2]), "+f"(d[tt][3])
                    : "r"(a0), "r"(a1), "r"(a2), "r"(a3),
                      "r"(bf0[t]), "r"(bf1[t]));
            }
#pragma unroll
            for (int tt = 0; tt < 8; tt++) {
                int t  = half * 8 + tt;
                int n0 = h * 128 + t * 8 + (lane & 3) * 2;
                unsigned p01, p23;
                CVT_F16X2(p01, d[tt][0], d[tt][1]);
                CVT_F16X2(p23, d[tt][2], d[tt][3]);
                *reinterpret_cast<unsigned*>(ob + row * OROW + n0 * 2) = p01;
                *reinterpret_cast<unsigned*>(ob + (row + 8) * OROW + n0 * 2) = p23;
            }
        }
        __syncthreads();

        // ---- coalesced readout: smemO -> g_table ----
        {
            int nloc = tid >> 2;
            int j0   = tid & 3;
            int node = bt * 16 + nloc;
            if (node < n_nodes) {
                const char* src = smemO + (nloc >> 4) * OTILE + (nloc & 15) * OROW;
#pragma unroll
                for (int jj = 0; jj < 8; jj++) {
                    int j = j0 + jj * 4;
                    uint4 val = *reinterpret_cast<const uint4*>(src + j * 16);
                    tb4[(size_t)node * 32 + j] = val;
                }
            }
        }
    }
}

// ---------------------------------------------------------------------------
// Kernel 2: edge (proven 38.4us config).
// ---------------------------------------------------------------------------
#define EPB 128
__global__ __launch_bounds__(256) void edge_kernel(
    const int* __restrict__ ei,
    const float* __restrict__ attr,
    float* __restrict__ out,
    int n_edges)
{
    int tid = threadIdx.x;
    int sl  = tid & 3;
    int g   = tid >> 2;

    const uint4* tb = reinterpret_cast<const uint4*>(g_table);

    int  e[2];
    e[0] = (int)(blockIdx.x * EPB) + g;
    e[1] = e[0] + 64;
    bool val[2];
    int  row[2];
    uint4 u0[2], u1[2];
    float wa[2], wb[2];

#pragma unroll
    for (int i = 0; i < 2; i++) {
        val[i] = (e[i] < n_edges);
        int ec = val[i] ? e[i] : (n_edges - 1);

        row[i]   = ei[ec];
        int col  = ei[n_edges + ec];
        float2 a = reinterpret_cast<const float2*>(attr)[ec];

        float sx = fmaf(a.x, 1.5f, 1.5f);
        float sy = fmaf(a.y, 1.5f, 1.5f);
        float ixf = fminf(fmaxf(floorf(sx), 0.f), 2.f);
        float iyf = fminf(fmaxf(floorf(sy), 0.f), 2.f);
        float fx = sx - ixf;
        float fy = sy - iyf;
        int iu = (int)ixf;
        int iv = (int)iyf;

        float w11 = fx * fy;
        float w10 = fx - w11;
        float w01 = fy - w11;
        float w00 = 1.f - fx - fy + w11;

        wa[i] = (sl < 2) ? w00 : w01;   // u = iu
        wb[i] = (sl < 2) ? w10 : w11;   // u = iu+1

        size_t bi = (size_t)col * 32 + (iu * 4 + iv) * 2 + sl;
        u0[i] = tb[bi];
        u1[i] = tb[bi + 8];
    }

#pragma unroll
    for (int i = 0; i < 2; i++) {
        const __half2* h0 = reinterpret_cast<const __half2*>(&u0[i]);
        const __half2* h1 = reinterpret_cast<const __half2*>(&u1[i]);
        float p[8];
#pragma unroll
        for (int j = 0; j < 4; j++) {
            float2 f0 = __half22float2(h0[j]);
            float2 f1 = __half22float2(h1[j]);
            p[2 * j]     = fmaf(wa[i], f0.x, wb[i] * f1.x);
            p[2 * j + 1] = fmaf(wa[i], f0.y, wb[i] * f1.y);
        }
        bool hi = (sl & 2);
        float fin0, fin1, fin2, fin3;
        {
            float s0 = hi ? p[0] : p[4];
            float s1 = hi ? p[1] : p[5];
            float s2 = hi ? p[2] : p[6];
            float s3 = hi ? p[3] : p[7];
            float r0 = __shfl_xor_sync(0xffffffffu, s0, 2);
            float r1 = __shfl_xor_sync(0xffffffffu, s1, 2);
            float r2 = __shfl_xor_sync(0xffffffffu, s2, 2);
            float r3 = __shfl_xor_sync(0xffffffffu, s3, 2);
            fin0 = (hi ? p[4] : p[0]) + r0;
            fin1 = (hi ? p[5] : p[1]) + r1;
            fin2 = (hi ? p[6] : p[2]) + r2;
            fin3 = (hi ? p[7] : p[3]) + r3;
        }
        if (val[i]) {
            int quad = (sl & 1) * 2 + (sl >> 1);
            float* op = out + (size_t)row[i] * F + quad * 4;
            asm volatile("red.global.add.v4.f32 [%0], {%1, %2, %3, %4};"
                         :: "l"(op), "f"(fin0), "f"(fin1), "f"(fin2), "f"(fin3)
                         : "memory");
        }
    }
}

// ---------------------------------------------------------------------------
extern "C" void kernel_launch(void* const* d_in, const int* in_sizes, int n_in,
                              void* d_out, int out_size)
{
    const float* x    = (const float*)d_in[0];
    const int*   ei   = (const int*)d_in[1];
    const float* attr = (const float*)d_in[2];
    const float* w    = (const float*)d_in[3];
    float*       out  = (float*)d_out;

    int n_nodes = in_sizes[0] / F;       // 100000
    int n_edges = in_sizes[1] / 2;       // 1600000

    cudaMemsetAsync(d_out, 0, (size_t)out_size * sizeof(float));

    build_table_kernel<<<320, 256>>>(x, w, n_nodes);

    int ek_blocks = (n_edges + EPB - 1) / EPB;
    edge_kernel<<<ek_blocks, 256>>>(ei, attr, out, n_edges);
}